// round 5
// baseline (speedup 1.0000x reference)
#include <cuda_runtime.h>
#include <cstdint>

// LinearTPReadOut: out[n] = w_tp/sqrt(3) * (1/128) * sum_i A_i(n)*B_i(n)
//   A_i(n) = sum_u x[n, 128+3u+i] * w_lin[u,0],  B_i with w_lin[u,1]
// x: (N,1152) f32, w_lin: (128,2) f32, w_tp: (1,) f32, out: (N,) f32
//
// One warp per row (8 rows sequentially per warp). Dense-coalesced loads:
// lane l reads float4 indices {l, l+32, l+64} of the 384-float span
// (3x LDG.128, 4 wavefronts each = optimal coalescing). Channel rotation:
// position e = 128j+4l+c has channel i = ((c+2j)%3 + l%3)%3; accumulate into
// rot[(c+2j)%3] (compile-time reg), un-rotate with SELs.
// Weights come from per-position expanded smem arrays via asm-volatile
// LDS.128 (deliberately NOT register-resident -> ~34 regs, high occupancy).
// Reduction: butterfly all-reduce the 3 B channels (15 shfl), per-lane
// p = sum_i rA_i * B, reduce p (5 shfl) -> 20 shfl/row total.

#define ROW_STRIDE_F   1152
#define ROW_STRIDE_V4  288
#define COL_OFF        128
#define ROWS_PER_WARP  8

#define LDS128(r0, r1, r2, r3, addr)                                  \
    asm volatile("ld.shared.v4.f32 {%0,%1,%2,%3}, [%4];"              \
                 : "=f"(r0), "=f"(r1), "=f"(r2), "=f"(r3) : "r"(addr))

__global__ __launch_bounds__(256)
void lintp_kernel(const float* __restrict__ x,
                  const float* __restrict__ w_lin,
                  const float* __restrict__ w_tp,
                  float* __restrict__ out, int n)
{
    __shared__ float wexp[2][384];   // [0][e]=w0[e/3], [1][e]=w1[e/3]

    const int tid  = threadIdx.x;
    const int lane = tid & 31;

    for (int e = tid; e < 384; e += 256) {
        const float2 p = *reinterpret_cast<const float2*>(w_lin + 2 * (e / 3));
        wexp[0][e] = p.x;
        wexp[1][e] = p.y;
    }
    __syncthreads();

    const int warpGlobal = (blockIdx.x * blockDim.x + tid) >> 5;
    const int row0 = warpGlobal * ROWS_PER_WARP;
    if (row0 >= n) return;

    const uint32_t wA = (uint32_t)__cvta_generic_to_shared(&wexp[0][0]) + lane * 16u;
    const uint32_t wB = wA + 1536u;

    const float scale = __ldg(w_tp) * 0.57735026918962576451f * (1.0f / 128.0f);
    const int s = lane % 3;

    const float4* xbase = reinterpret_cast<const float4*>(
        x + (size_t)row0 * ROW_STRIDE_F + COL_OFF) + lane;

    #pragma unroll
    for (int r = 0; r < ROWS_PER_WARP; r++) {
        const int row = row0 + r;
        if (row >= n) break;                        // warp-uniform
        const float4* xp = xbase + (size_t)r * ROW_STRIDE_V4;
        const float4 v0 = xp[0];
        const float4 v1 = xp[32];
        const float4 v2 = xp[64];

        float rA0, rA1, rA2, rB0, rB1, rB2;
        float a0, a1, a2, a3, b0, b1, b2, b3;

        // j=0: rot index k = c%3 -> 0,1,2,0
        LDS128(a0, a1, a2, a3, wA);
        LDS128(b0, b1, b2, b3, wB);
        rA0 = v0.x * a0;             rB0 = v0.x * b0;
        rA1 = v0.y * a1;             rB1 = v0.y * b1;
        rA2 = v0.z * a2;             rB2 = v0.z * b2;
        rA0 = fmaf(v0.w, a3, rA0);   rB0 = fmaf(v0.w, b3, rB0);

        // j=1: k = (c+2)%3 -> 2,0,1,2
        LDS128(a0, a1, a2, a3, wA + 512u);
        LDS128(b0, b1, b2, b3, wB + 512u);
        rA2 = fmaf(v1.x, a0, rA2);   rB2 = fmaf(v1.x, b0, rB2);
        rA0 = fmaf(v1.y, a1, rA0);   rB0 = fmaf(v1.y, b1, rB0);
        rA1 = fmaf(v1.z, a2, rA1);   rB1 = fmaf(v1.z, b2, rB1);
        rA2 = fmaf(v1.w, a3, rA2);   rB2 = fmaf(v1.w, b3, rB2);

        // j=2: k = (c+1)%3 -> 1,2,0,1
        LDS128(a0, a1, a2, a3, wA + 1024u);
        LDS128(b0, b1, b2, b3, wB + 1024u);
        rA1 = fmaf(v2.x, a0, rA1);   rB1 = fmaf(v2.x, b0, rB1);
        rA2 = fmaf(v2.y, a1, rA2);   rB2 = fmaf(v2.y, b1, rB2);
        rA0 = fmaf(v2.z, a2, rA0);   rB0 = fmaf(v2.z, b2, rB0);
        rA1 = fmaf(v2.w, a3, rA1);   rB1 = fmaf(v2.w, b3, rB1);

        // un-rotate B to absolute channels: B_i = rot[(i - s) mod 3]
        float B0 = (s == 0) ? rB0 : ((s == 1) ? rB2 : rB1);
        float B1 = (s == 0) ? rB1 : ((s == 1) ? rB0 : rB2);
        float B2 = (s == 0) ? rB2 : ((s == 1) ? rB1 : rB0);

        // butterfly all-reduce B over the warp (every lane gets full sums)
        #pragma unroll
        for (int m = 16; m > 0; m >>= 1) {
            B0 += __shfl_xor_sync(0xffffffffu, B0, m);
            B1 += __shfl_xor_sync(0xffffffffu, B1, m);
            B2 += __shfl_xor_sync(0xffffffffu, B2, m);
        }

        // per-lane partial of sum_i A_i*B_i: rA_j holds channel (j+s)%3
        const float Bs0 = (s == 0) ? B0 : ((s == 1) ? B1 : B2);
        const float Bs1 = (s == 0) ? B1 : ((s == 1) ? B2 : B0);
        const float Bs2 = (s == 0) ? B2 : ((s == 1) ? B0 : B1);
        float p = rA0 * Bs0;
        p = fmaf(rA1, Bs1, p);
        p = fmaf(rA2, Bs2, p);

        #pragma unroll
        for (int m = 16; m > 0; m >>= 1)
            p += __shfl_down_sync(0xffffffffu, p, m);

        if (lane == 0)
            out[row] = scale * p;
    }
}

extern "C" void kernel_launch(void* const* d_in, const int* in_sizes, int n_in,
                              void* d_out, int out_size)
{
    const float* x     = (const float*)d_in[0];
    const float* w_lin = (const float*)d_in[1];
    const float* w_tp  = (const float*)d_in[2];
    float* out = (float*)d_out;

    const int n = in_sizes[0] / ROW_STRIDE_F;        // 200000
    const int rowsPerBlock = 8 * ROWS_PER_WARP;      // 64
    const int blocks = (n + rowsPerBlock - 1) / rowsPerBlock;
    lintp_kernel<<<blocks, 256>>>(x, w_lin, w_tp, out, n);
}

// round 8
// speedup vs baseline: 1.5648x; 1.5648x over previous
#include <cuda_runtime.h>
#include <cstdint>

// LinearTPReadOut: out[n] = w_tp/sqrt(3) * (1/128) * sum_i A_i(n)*B_i(n)
//   A_i(n) = sum_u x[n, 128+3u+i] * w_lin[u,0],  B_i with w_lin[u,1]
// x: (N,1152) f32, w_lin: (128,2) f32, w_tp: (1,) f32, out: (N,) f32
//
// Two-phase per block:
//   1) cp.async.cg (L1-bypass) dense stage of 16 rows x 384 floats -> smem.
//      Each warp's 32 consecutive float4s lie inside one row (96 f4 = 3
//      warps/row) -> perfect 4-sector wavefronts, zero L1tex pressure.
//   2) Compute with R1's per-lane u-aligned mapping (lane l owns u=4l..4l+3,
//      12 floats at 48B stride) from smem. Conflict-free: LDS.128 phase of
//      8 lanes hits word banks {12l mod 32} = all 32 banks exactly once.
//      Weights: 8 regs/lane (2x LDG.128, L1-hit). No channel rotation.
// Reduction: butterfly all-reduce B (15 shfl) + per-lane dot + reduce p
// (5 shfl) = 20 shfl/row.

#define ROW_STRIDE_F 1152
#define COL_OFF      128
#define TILE_ROWS    16
#define SPAN_F4      96        // 384 floats / 4

__global__ __launch_bounds__(256)
void lintp_kernel(const float* __restrict__ x,
                  const float* __restrict__ w_lin,
                  const float* __restrict__ w_tp,
                  float* __restrict__ out, int n)
{
    __shared__ float tile[TILE_ROWS * 384];

    const int tid  = threadIdx.x;
    const int lane = tid & 31;
    const int warp = tid >> 5;
    const int row0 = blockIdx.x * TILE_ROWS;

    // ---- per-lane weights (R1 mapping: u = 4l .. 4l+3), 8 regs ----
    const float4* wp = reinterpret_cast<const float4*>(w_lin) + 2 * lane;
    const float4 wA = __ldg(wp);      // w0[4l], w1[4l], w0[4l+1], w1[4l+1]
    const float4 wB = __ldg(wp + 1);  // w0[4l+2], w1[4l+2], w0[4l+3], w1[4l+3]
    const float scale = __ldg(w_tp) * 0.57735026918962576451f * (1.0f / 128.0f);

    // ---- stage 16 rows densely via cp.async.cg (bypasses L1) ----
    const uint32_t sbase = (uint32_t)__cvta_generic_to_shared(tile);
    #pragma unroll
    for (int k = 0; k < 6; k++) {
        const int f    = tid + 256 * k;       // float4 index in tile [0,1536)
        const int lrow = f / SPAN_F4;
        const int col  = f - lrow * SPAN_F4;  // float4 col within span
        const int grow = row0 + lrow;
        if (grow < n) {
            const float* gp = x + (size_t)grow * ROW_STRIDE_F + COL_OFF + 4 * col;
            asm volatile("cp.async.cg.shared.global [%0], [%1], 16;"
                         :: "r"(sbase + 16u * (uint32_t)f), "l"(gp));
        }
    }
    asm volatile("cp.async.commit_group;");
    asm volatile("cp.async.wait_group 0;");
    __syncthreads();

    // ---- compute: warp w handles local rows 2w, 2w+1 ----
    #pragma unroll
    for (int rr = 0; rr < 2; rr++) {
        const int lrow = 2 * warp + rr;
        const int grow = row0 + lrow;

        const float4* tp = reinterpret_cast<const float4*>(
            &tile[lrow * 384 + 12 * lane]);
        const float4 v0 = tp[0];
        const float4 v1 = tp[1];
        const float4 v2 = tp[2];

        // index map (12 floats = 4 u-groups of 3 channels):
        //  v0 = {u0i0, u0i1, u0i2, u1i0}
        //  v1 = {u1i1, u1i2, u2i0, u2i1}
        //  v2 = {u2i2, u3i0, u3i1, u3i2}
        const float A0 = v0.x*wA.x + v0.w*wA.z + v1.z*wB.x + v2.y*wB.z;
        const float A1 = v0.y*wA.x + v1.x*wA.z + v1.w*wB.x + v2.z*wB.z;
        const float A2 = v0.z*wA.x + v1.y*wA.z + v2.x*wB.x + v2.w*wB.z;
        float B0 = v0.x*wA.y + v0.w*wA.w + v1.z*wB.y + v2.y*wB.w;
        float B1 = v0.y*wA.y + v1.x*wA.w + v1.w*wB.y + v2.z*wB.w;
        float B2 = v0.z*wA.y + v1.y*wA.w + v2.x*wB.y + v2.w*wB.w;

        // butterfly all-reduce B over the warp
        #pragma unroll
        for (int m = 16; m > 0; m >>= 1) {
            B0 += __shfl_xor_sync(0xffffffffu, B0, m);
            B1 += __shfl_xor_sync(0xffffffffu, B1, m);
            B2 += __shfl_xor_sync(0xffffffffu, B2, m);
        }

        float p = A0 * B0;
        p = fmaf(A1, B1, p);
        p = fmaf(A2, B2, p);

        #pragma unroll
        for (int m = 16; m > 0; m >>= 1)
            p += __shfl_down_sync(0xffffffffu, p, m);

        if (lane == 0 && grow < n)
            out[grow] = scale * p;
    }
}

extern "C" void kernel_launch(void* const* d_in, const int* in_sizes, int n_in,
                              void* d_out, int out_size)
{
    const float* x     = (const float*)d_in[0];
    const float* w_lin = (const float*)d_in[1];
    const float* w_tp  = (const float*)d_in[2];
    float* out = (float*)d_out;

    const int n = in_sizes[0] / ROW_STRIDE_F;            // 200000
    const int blocks = (n + TILE_ROWS - 1) / TILE_ROWS;  // 12500
    lintp_kernel<<<blocks, 256>>>(x, w_lin, w_tp, out, n);
}